// round 2
// baseline (speedup 1.0000x reference)
#include <cuda_runtime.h>
#include <cstdint>
#include <cstddef>

constexpr int kN   = 32;
constexpr int kC   = 256;
constexpr int kT   = 64;
constexpr int kV   = 25;
constexpr int kH   = 8;
constexpr int kWIN = 5;
constexpr int kB   = kN * kT;        // 2048 windows
constexpr int kL   = kWIN * kV;      // 125
constexpr int kU   = kB * kV;        // 51200 unique tokens
constexpr int kM1  = kU + 1;         // + pad row
constexpr int kTV  = kT * kV;        // 1600
constexpr int kXN  = kC * kTV;       // 409600
constexpr float kSCALE = 0.17677669529663687f;  // 1/sqrt(32)

// ---------------- scratch (device globals; reused across stages) ----------------
__device__ float g_nx [(size_t)kM1 * kC];   // nx -> mq -> h1
__device__ float g_q  [(size_t)kM1 * kC];   // q  -> t1
__device__ float g_k  [(size_t)kM1 * kC];   // k  -> attraw
__device__ float g_v  [(size_t)kM1 * kC];   // v  -> f
__device__ float g_xr [(size_t)kU  * kC];   // gathered x (residual)
__device__ float g_mkv[(size_t)kU  * kC];   // mkv -> y
__device__ float g_ql [(size_t)kM1 * kH];   // q attention logits

// ============ LN over C of unique tokens (gather from x) + write raw xr ============
__global__ void __launch_bounds__(256) k_ln_x(const float* __restrict__ x,
                                              const float* __restrict__ g,
                                              const float* __restrict__ b) {
    __shared__ float sx[32][257];
    int tid = threadIdx.x;
    int u0  = blockIdx.x * 32;
    {
        int ur = tid & 31;
        int u  = u0 + ur;
        int cb = tid >> 5;
        bool has = (u < kU);
        size_t base = 0;
        if (has) { int n = u / kTV; base = (size_t)n * kXN + (u - n * kTV); }
#pragma unroll
        for (int j = 0; j < 32; j++) {
            int c = cb * 32 + j;
            sx[ur][c] = has ? x[base + (size_t)c * kTV] : 0.f;
        }
    }
    __syncthreads();
    int lane = tid & 31, warp = tid >> 5;
#pragma unroll
    for (int rr = 0; rr < 4; rr++) {
        int ur = warp * 4 + rr;
        int u  = u0 + ur;
        if (u >= kM1) continue;
        float vals[8];
        float s = 0.f, sq = 0.f;
#pragma unroll
        for (int j = 0; j < 8; j++) {
            float t = sx[ur][lane + 32 * j];
            vals[j] = t; s += t; sq += t * t;
        }
#pragma unroll
        for (int o = 16; o; o >>= 1) {
            s  += __shfl_xor_sync(0xffffffffu, s,  o);
            sq += __shfl_xor_sync(0xffffffffu, sq, o);
        }
        float mean = s * (1.f / kC);
        float var  = sq * (1.f / kC) - mean * mean;
        float rstd = rsqrtf(var + 1e-5f);
#pragma unroll
        for (int j = 0; j < 8; j++) {
            int c = lane + 32 * j;
            g_nx[(size_t)u * kC + c] = (vals[j] - mean) * rstd * g[c] + b[c];
            if (u < kU) g_xr[(size_t)u * kC + c] = vals[j];
        }
    }
}

// ============ tf32 tensor-core GEMM: D = A(MxK=256) @ W(256x256) + bias ============
// EPI: 0 = bias ; 1 = bias + addm ; 2 = gelu(bias + acc)
constexpr int PITCH = 136;

__device__ __forceinline__ uint32_t f2tf(float f) {
    uint32_t r; asm("cvt.rna.tf32.f32 %0, %1;" : "=r"(r) : "f"(f)); return r;
}
__device__ __forceinline__ void mma_tf32(float (&d)[4], const uint32_t (&a)[4],
                                         const uint32_t (&bb)[2]) {
    asm volatile(
        "mma.sync.aligned.m16n8k8.row.col.f32.tf32.tf32.f32 "
        "{%0,%1,%2,%3}, {%4,%5,%6,%7}, {%8,%9}, {%0,%1,%2,%3};\n"
        : "+f"(d[0]), "+f"(d[1]), "+f"(d[2]), "+f"(d[3])
        : "r"(a[0]), "r"(a[1]), "r"(a[2]), "r"(a[3]), "r"(bb[0]), "r"(bb[1]));
}
__device__ __forceinline__ float gelu_exact(float x) {
    return 0.5f * x * (1.0f + erff(x * 0.70710678118654752f));
}

template<int EPI>
__global__ void __launch_bounds__(256) k_gemm(const float* __restrict__ A,
                                              const float* __restrict__ W,
                                              const float* __restrict__ bias,
                                              const float* __restrict__ addm,
                                              float* __restrict__ D, int M) {
    __shared__ float As[32 * PITCH];
    __shared__ float Bs[32 * PITCH];
    int tid = threadIdx.x, lane = tid & 31, warp = tid >> 5;
    int wm = warp >> 1, wn = warp & 1;           // 4x2 warp grid, warp tile 32x64
    int row0 = blockIdx.x * 128, col0 = blockIdx.y * 128;
    int p = lane >> 2, q = lane & 3;

    float acc[2][8][4] = {};

    int ar = tid >> 1;                  // A: row within tile
    int ak = (tid & 1) * 16;            // A: k base
    int bk = tid >> 3;                  // B: k row
    int bn = (tid & 7) * 16;            // B: n base
    bool arow_ok = (row0 + ar) < M;
    const float* Abase = A + (size_t)(row0 + ar) * kC + ak;
    const float* Wbase = W + (size_t)bk * kC + col0 + bn;

    for (int kt = 0; kt < 8; kt++) {
#pragma unroll
        for (int i = 0; i < 4; i++) {
            float4 t4 = arow_ok ? *(const float4*)(Abase + kt * 32 + 4 * i)
                                : make_float4(0.f, 0.f, 0.f, 0.f);
            As[(ak + 4 * i + 0) * PITCH + ar] = t4.x;
            As[(ak + 4 * i + 1) * PITCH + ar] = t4.y;
            As[(ak + 4 * i + 2) * PITCH + ar] = t4.z;
            As[(ak + 4 * i + 3) * PITCH + ar] = t4.w;
        }
#pragma unroll
        for (int i = 0; i < 4; i++) {
            float4 t4 = *(const float4*)(Wbase + (size_t)kt * 32 * kC + 4 * i);
            *(float4*)&Bs[bk * PITCH + bn + 4 * i] = t4;
        }
        __syncthreads();
#pragma unroll
        for (int kk = 0; kk < 32; kk += 8) {
            uint32_t af[2][4], bf[8][2];
#pragma unroll
            for (int mi = 0; mi < 2; mi++) {
                int m = wm * 32 + mi * 16 + p;
                af[mi][0] = f2tf(As[(kk + q) * PITCH + m]);
                af[mi][1] = f2tf(As[(kk + q) * PITCH + m + 8]);
                af[mi][2] = f2tf(As[(kk + q + 4) * PITCH + m]);
                af[mi][3] = f2tf(As[(kk + q + 4) * PITCH + m + 8]);
            }
#pragma unroll
            for (int ni = 0; ni < 8; ni++) {
                int nn = wn * 64 + ni * 8 + p;
                bf[ni][0] = f2tf(Bs[(kk + q) * PITCH + nn]);
                bf[ni][1] = f2tf(Bs[(kk + q + 4) * PITCH + nn]);
            }
#pragma unroll
            for (int mi = 0; mi < 2; mi++)
#pragma unroll
                for (int ni = 0; ni < 8; ni++)
                    mma_tf32(acc[mi][ni], af[mi], bf[ni]);
        }
        __syncthreads();
    }

#pragma unroll
    for (int mi = 0; mi < 2; mi++) {
        int r1 = row0 + wm * 32 + mi * 16 + p;
        int r2 = r1 + 8;
#pragma unroll
        for (int ni = 0; ni < 8; ni++) {
            int cc = col0 + wn * 64 + ni * 8 + 2 * q;
            float2 bv = *(const float2*)(bias + cc);
            float d0 = acc[mi][ni][0] + bv.x, d1 = acc[mi][ni][1] + bv.y;
            float d2 = acc[mi][ni][2] + bv.x, d3 = acc[mi][ni][3] + bv.y;
            if (EPI == 1) {
                if (r1 < M) { float2 a1 = *(const float2*)(addm + (size_t)r1 * kC + cc); d0 += a1.x; d1 += a1.y; }
                if (r2 < M) { float2 a2 = *(const float2*)(addm + (size_t)r2 * kC + cc); d2 += a2.x; d3 += a2.y; }
            }
            if (EPI == 2) {
                d0 = gelu_exact(d0); d1 = gelu_exact(d1);
                d2 = gelu_exact(d2); d3 = gelu_exact(d3);
            }
            if (r1 < M) { float2 o; o.x = d0; o.y = d1; *(float2*)(D + (size_t)r1 * kC + cc) = o; }
            if (r2 < M) { float2 o; o.x = d2; o.y = d3; *(float2*)(D + (size_t)r2 * kC + cc) = o; }
        }
    }
}

// ============ q attention logits: qlog[r][h] = scale*(q[r]·qa_w[:,h] + qa_b[h]) ============
__global__ void __launch_bounds__(256) k_qlog(const float* __restrict__ qa_w,
                                              const float* __restrict__ qa_b, int M) {
    int warp = threadIdx.x >> 5, lane = threadIdx.x & 31;
    int r = blockIdx.x * 8 + warp;
    if (r >= M) return;
    const float* row = g_q + (size_t)r * kC;
    int c0 = lane * 8;
    float4 v0 = *(const float4*)(row + c0);
    float4 v1 = *(const float4*)(row + c0 + 4);
    float vv[8] = {v0.x, v0.y, v0.z, v0.w, v1.x, v1.y, v1.z, v1.w};
    float acc[8] = {};
#pragma unroll
    for (int j = 0; j < 8; j++) {
        const float4* wr = (const float4*)(qa_w + (size_t)(c0 + j) * kH);
        float4 w0 = wr[0], w1 = wr[1];
        acc[0] += vv[j] * w0.x; acc[1] += vv[j] * w0.y;
        acc[2] += vv[j] * w0.z; acc[3] += vv[j] * w0.w;
        acc[4] += vv[j] * w1.x; acc[5] += vv[j] * w1.y;
        acc[6] += vv[j] * w1.z; acc[7] += vv[j] * w1.w;
    }
#pragma unroll
    for (int o = 16; o; o >>= 1)
#pragma unroll
        for (int e = 0; e < 8; e++)
            acc[e] += __shfl_xor_sync(0xffffffffu, acc[e], o);
    if (lane < 8) g_ql[(size_t)r * kH + lane] = (acc[lane] + qa_b[lane]) * kSCALE;
}

// ============ fused per-window pooling: qw,pq,klog,kw,pk -> mq, mkv ============
__global__ void __launch_bounds__(256) k_pool(const float* __restrict__ ka_w,
                                              const float* __restrict__ ka_b) {
    __shared__ int   su[kL];
    __shared__ float sqw[kH][128];
    __shared__ float skw[kH][128];
    __shared__ float spq[kC];
    int tid = threadIdx.x, lane = tid & 31, h = tid >> 5;
    int b = blockIdx.x, n = b / kT, t = b % kT;

    if (tid < kL) {
        int w = tid / kV, v = tid - w * kV;
        int tp = t + w - 2;
        su[tid] = (tp >= 0 && tp < kT) ? (n * kT + tp) * kV + v : kU;
    }
    // preload ka_w columns for this lane's channels (c = lane + 32j)
    float wreg[8][8];
#pragma unroll
    for (int j = 0; j < 8; j++) {
        int c = lane + 32 * j;
        const float4* wr = (const float4*)(ka_w + (size_t)c * kH);
        float4 w0 = wr[0], w1 = wr[1];
        wreg[j][0] = w0.x; wreg[j][1] = w0.y; wreg[j][2] = w0.z; wreg[j][3] = w0.w;
        wreg[j][4] = w1.x; wreg[j][5] = w1.y; wreg[j][6] = w1.z; wreg[j][7] = w1.w;
    }
    float kab = (lane < kH) ? ka_b[lane] : 0.f;
    __syncthreads();

    // ---- q-weight softmax (warp h over l) ----
    {
        float lv[4]; float mx = -1e30f;
#pragma unroll
        for (int i = 0; i < 4; i++) {
            int l = lane + 32 * i;
            lv[i] = (l < kL) ? g_ql[(size_t)su[l] * kH + h] : -1e30f;
            mx = fmaxf(mx, lv[i]);
        }
#pragma unroll
        for (int o = 16; o; o >>= 1) mx = fmaxf(mx, __shfl_xor_sync(0xffffffffu, mx, o));
        float sm = 0.f;
#pragma unroll
        for (int i = 0; i < 4; i++) {
            int l = lane + 32 * i;
            lv[i] = (l < kL) ? expf(lv[i] - mx) : 0.f;
            sm += lv[i];
        }
#pragma unroll
        for (int o = 16; o; o >>= 1) sm += __shfl_xor_sync(0xffffffffu, sm, o);
        float inv = 1.f / sm;
#pragma unroll
        for (int i = 0; i < 4; i++) {
            int l = lane + 32 * i;
            if (l < kL) sqw[h][l] = lv[i] * inv;
        }
    }
    __syncthreads();

    // ---- pass A: pq (softmax-pooled q) and mq (window-mean q) ----
    float pq = 0.f;
#pragma unroll
    for (int v = 0; v < kV; v++) {
        float a = 0.f;
#pragma unroll
        for (int w = 0; w < kWIN; w++) {
            int l = w * kV + v;
            float val = g_q[(size_t)su[l] * kC + tid];
            pq += sqw[h][l] * val;
            a  += val;
        }
        g_nx[((size_t)b * kV + v) * kC + tid] = a * 0.2f;   // mq (reuses g_nx)
    }
    spq[tid] = pq;
    __syncthreads();

    // ---- pass B: k logits (warp per l, strided) ----
    float pqr[8];
#pragma unroll
    for (int j = 0; j < 8; j++) pqr[j] = spq[lane + 32 * j];
    for (int l = h; l < kL; l += kH) {
        const float* kr = g_k + (size_t)su[l] * kC;
        float acc[8] = {};
#pragma unroll
        for (int j = 0; j < 8; j++) {
            float kp = kr[lane + 32 * j] * pqr[j];
#pragma unroll
            for (int e = 0; e < 8; e++) acc[e] += kp * wreg[j][e];
        }
#pragma unroll
        for (int o = 16; o; o >>= 1)
#pragma unroll
            for (int e = 0; e < 8; e++)
                acc[e] += __shfl_xor_sync(0xffffffffu, acc[e], o);
        if (lane < kH) skw[lane][l] = (acc[lane] + kab) * kSCALE;
    }
    __syncthreads();

    // ---- k-weight softmax (warp h over l, in place) ----
    {
        float lv[4]; float mx = -1e30f;
#pragma unroll
        for (int i = 0; i < 4; i++) {
            int l = lane + 32 * i;
            lv[i] = (l < kL) ? skw[h][l] : -1e30f;
            mx = fmaxf(mx, lv[i]);
        }
#pragma unroll
        for (int o = 16; o; o >>= 1) mx = fmaxf(mx, __shfl_xor_sync(0xffffffffu, mx, o));
        float sm = 0.f;
#pragma unroll
        for (int i = 0; i < 4; i++) {
            int l = lane + 32 * i;
            lv[i] = (l < kL) ? expf(lv[i] - mx) : 0.f;
            sm += lv[i];
        }
#pragma unroll
        for (int o = 16; o; o >>= 1) sm += __shfl_xor_sync(0xffffffffu, sm, o);
        float inv = 1.f / sm;
#pragma unroll
        for (int i = 0; i < 4; i++) {
            int l = lane + 32 * i;
            if (l < kL) skw[h][l] = lv[i] * inv;
        }
    }
    __syncthreads();

    // ---- pass C: pk (softmax-pooled k), mv (window-mean v), then mkv = pk*mv ----
    float pk = 0.f;
    float mva[kV];
#pragma unroll
    for (int v = 0; v < kV; v++) {
        float a = 0.f;
#pragma unroll
        for (int w = 0; w < kWIN; w++) {
            int l = w * kV + v;
            int u = su[l];
            pk += skw[h][l] * g_k[(size_t)u * kC + tid];
            a  += g_v[(size_t)u * kC + tid];
        }
        mva[v] = a * 0.2f;
    }
#pragma unroll
    for (int v = 0; v < kV; v++)
        g_mkv[((size_t)b * kV + v) * kC + tid] = pk * mva[v];
}

// ============ plain row LayerNorm (FFN input): g_k(attraw) -> g_v(f) ============
__global__ void __launch_bounds__(256) k_ln_rows(const float* __restrict__ g,
                                                 const float* __restrict__ b) {
    int warp = threadIdx.x >> 5, lane = threadIdx.x & 31;
    int r = blockIdx.x * 8 + warp;
    const float* row = g_k + (size_t)r * kC;
    float vv[8]; float s = 0.f, sq = 0.f;
#pragma unroll
    for (int j = 0; j < 8; j++) {
        float x = row[lane + 32 * j];
        vv[j] = x; s += x; sq += x * x;
    }
#pragma unroll
    for (int o = 16; o; o >>= 1) {
        s  += __shfl_xor_sync(0xffffffffu, s,  o);
        sq += __shfl_xor_sync(0xffffffffu, sq, o);
    }
    float mean = s * (1.f / kC);
    float var  = sq * (1.f / kC) - mean * mean;
    float rstd = rsqrtf(var + 1e-5f);
#pragma unroll
    for (int j = 0; j < 8; j++) {
        int c = lane + 32 * j;
        g_v[(size_t)r * kC + c] = (vv[j] - mean) * rstd * g[c] + b[c];
    }
}

// ============ transpose y (u,c) -> out (n,c,t,v) ============
__global__ void __launch_bounds__(256) k_out(float* __restrict__ out) {
    __shared__ float sy[kV][257];
    int b = blockIdx.x, n = b / kT, t = b % kT;
    int tid = threadIdx.x;
#pragma unroll
    for (int v = 0; v < kV; v++)
        sy[v][tid] = g_mkv[((size_t)b * kV + v) * kC + tid];
    __syncthreads();
    float* ob = out + (size_t)n * kXN + t * kV;
    for (int i = tid; i < kV * kC; i += 256) {
        int c = i / kV, v = i - c * kV;
        ob[(size_t)c * kTV + v] = sy[v][c];
    }
}

// ===================================================================================
extern "C" void kernel_launch(void* const* d_in, const int* in_sizes, int n_in,
                              void* d_out, int out_size) {
    const float* x    = (const float*)d_in[0];
    const float* ln1g = (const float*)d_in[1];
    const float* ln1b = (const float*)d_in[2];
    const float* q_w  = (const float*)d_in[3];
    const float* q_b  = (const float*)d_in[4];
    const float* qa_w = (const float*)d_in[5];
    const float* qa_b = (const float*)d_in[6];
    const float* k_w  = (const float*)d_in[7];
    const float* k_b  = (const float*)d_in[8];
    const float* ka_w = (const float*)d_in[9];
    const float* ka_b = (const float*)d_in[10];
    const float* v_w  = (const float*)d_in[11];
    const float* v_b  = (const float*)d_in[12];
    const float* t_w  = (const float*)d_in[13];
    const float* t_b  = (const float*)d_in[14];
    const float* p_w  = (const float*)d_in[15];
    const float* p_b  = (const float*)d_in[16];
    const float* ffng = (const float*)d_in[17];
    const float* ffnb = (const float*)d_in[18];
    const float* w1   = (const float*)d_in[19];
    const float* b1   = (const float*)d_in[20];
    const float* w2   = (const float*)d_in[21];
    const float* b2   = (const float*)d_in[22];
    float* out = (float*)d_out;

    float *p_nx, *p_q, *p_k, *p_v, *p_xr, *p_mkv;
    cudaGetSymbolAddress((void**)&p_nx,  g_nx);
    cudaGetSymbolAddress((void**)&p_q,   g_q);
    cudaGetSymbolAddress((void**)&p_k,   g_k);
    cudaGetSymbolAddress((void**)&p_v,   g_v);
    cudaGetSymbolAddress((void**)&p_xr,  g_xr);
    cudaGetSymbolAddress((void**)&p_mkv, g_mkv);

    dim3 g1((kM1 + 127) / 128, 2);
    dim3 g2((kU  + 127) / 128, 2);

    // 1) LN of unique tokens (+ raw gather for residual)
    k_ln_x<<<(kM1 + 31) / 32, 256>>>(x, ln1g, ln1b);
    // 2-4) q, k, v projections (rows = unique tokens + pad)
    k_gemm<0><<<g1, 256>>>(p_nx, q_w, q_b, nullptr, p_q, kM1);
    k_gemm<0><<<g1, 256>>>(p_nx, k_w, k_b, nullptr, p_k, kM1);
    k_gemm<0><<<g1, 256>>>(p_nx, v_w, v_b, nullptr, p_v, kM1);
    // 5) q attention logits
    k_qlog<<<(kM1 + 7) / 8, 256>>>(qa_w, qa_b, kM1);
    // 6) fused pooling -> mq (in g_nx), mkv
    k_pool<<<kB, 256>>>(ka_w, ka_b);
    // 7) t1 = mkv @ t_w + t_b + mq       (-> g_q)
    k_gemm<1><<<g2, 256>>>(p_mkv, t_w, t_b, p_nx, p_q, kU);
    // 8) attraw = t1 @ p_w + p_b + xr    (-> g_k)
    k_gemm<1><<<g2, 256>>>(p_q, p_w, p_b, p_xr, p_k, kU);
    // 9) f = LN(attraw)                  (-> g_v)
    k_ln_rows<<<kU / 8, 256>>>(ffng, ffnb);
    // 10) h1 = gelu(f @ w1 + b1)         (-> g_nx)
    k_gemm<2><<<g2, 256>>>(p_v, w1, b1, nullptr, p_nx, kU);
    // 11) y = h1 @ w2 + b2 + attraw      (-> g_mkv)
    k_gemm<1><<<g2, 256>>>(p_nx, w2, b2, p_k, p_mkv, kU);
    // 12) transpose to (N,C,T,V)
    k_out<<<kB, 256>>>(out);
}

// round 3
// speedup vs baseline: 1.2112x; 1.2112x over previous
#include <cuda_runtime.h>
#include <cstdint>
#include <cstddef>

constexpr int kN   = 32;
constexpr int kC   = 256;
constexpr int kT   = 64;
constexpr int kV   = 25;
constexpr int kH   = 8;
constexpr int kWIN = 5;
constexpr int kB   = kN * kT;        // 2048 windows
constexpr int kL   = kWIN * kV;      // 125
constexpr int kU   = kB * kV;        // 51200 unique tokens
constexpr int kM1  = kU + 1;         // + pad row
constexpr int kTV  = kT * kV;        // 1600
constexpr int kXN  = kC * kTV;       // 409600
constexpr float kSCALE = 0.17677669529663687f;  // 1/sqrt(32)

// ---------------- scratch (device globals; reused across stages) ----------------
__device__ float g_nx [(size_t)kM1 * kC];   // nx -> mq -> h1
__device__ float g_q  [(size_t)kM1 * kC];   // q  -> t1
__device__ float g_k  [(size_t)kM1 * kC];   // k  -> attraw
__device__ float g_v  [(size_t)kM1 * kC];   // v  -> f
__device__ float g_xr [(size_t)kU  * kC];   // gathered x (residual)
__device__ float g_mkv[(size_t)kU  * kC];   // mkv -> y
__device__ float g_ql [(size_t)kM1 * kH];   // q attention logits

// ============ LN over C of unique tokens (gather from x) + write raw xr ============
__global__ void __launch_bounds__(256) k_ln_x(const float* __restrict__ x,
                                              const float* __restrict__ g,
                                              const float* __restrict__ b) {
    __shared__ float sx[32][257];
    int tid = threadIdx.x;
    int u0  = blockIdx.x * 32;
    {
        int ur = tid & 31;
        int u  = u0 + ur;
        int cb = tid >> 5;
        bool has = (u < kU);
        size_t base = 0;
        if (has) { int n = u / kTV; base = (size_t)n * kXN + (u - n * kTV); }
#pragma unroll
        for (int j = 0; j < 32; j++) {
            int c = cb * 32 + j;
            sx[ur][c] = has ? x[base + (size_t)c * kTV] : 0.f;
        }
    }
    __syncthreads();
    int lane = tid & 31, warp = tid >> 5;
#pragma unroll
    for (int rr = 0; rr < 4; rr++) {
        int ur = warp * 4 + rr;
        int u  = u0 + ur;
        if (u >= kM1) continue;
        float vals[8];
        float s = 0.f, sq = 0.f;
#pragma unroll
        for (int j = 0; j < 8; j++) {
            float t = sx[ur][lane + 32 * j];
            vals[j] = t; s += t; sq += t * t;
        }
#pragma unroll
        for (int o = 16; o; o >>= 1) {
            s  += __shfl_xor_sync(0xffffffffu, s,  o);
            sq += __shfl_xor_sync(0xffffffffu, sq, o);
        }
        float mean = s * (1.f / kC);
        float var  = sq * (1.f / kC) - mean * mean;
        float rstd = rsqrtf(var + 1e-5f);
#pragma unroll
        for (int j = 0; j < 8; j++) {
            int c = lane + 32 * j;
            g_nx[(size_t)u * kC + c] = (vals[j] - mean) * rstd * g[c] + b[c];
            if (u < kU) g_xr[(size_t)u * kC + c] = vals[j];
        }
    }
}

// ============ tf32 tensor-core GEMM v2: D = A(MxK=256) @ W(256x256) + bias ============
// CTA tile 128(M) x 256(N=full), 8 warps (2x4), warp tile 64x64.
// Double-buffered cp.async for A and B. A smem [m][36], B smem [k][264].
// EPI: 0 = bias ; 1 = bias + addm ; 2 = gelu(bias + acc)
constexpr int APITCH = 36;    // floats per A row (32 + pad), 144B, 16B-aligned
constexpr int BPITCH = 264;   // floats per B row (256 + pad), 1056B, 16B-aligned
constexpr int ASZ = 128 * APITCH;   // 4608 floats per stage
constexpr int BSZ = 32 * BPITCH;    // 8448 floats per stage
constexpr int GEMM_SMEM = (2 * ASZ + 2 * BSZ) * 4;  // 104448 bytes

__device__ __forceinline__ uint32_t f2tf(float f) {
    uint32_t r; asm("cvt.rna.tf32.f32 %0, %1;" : "=r"(r) : "f"(f)); return r;
}
__device__ __forceinline__ void mma_tf32(float (&d)[4], const uint32_t (&a)[4],
                                         const uint32_t (&bb)[2]) {
    asm volatile(
        "mma.sync.aligned.m16n8k8.row.col.f32.tf32.tf32.f32 "
        "{%0,%1,%2,%3}, {%4,%5,%6,%7}, {%8,%9}, {%0,%1,%2,%3};\n"
        : "+f"(d[0]), "+f"(d[1]), "+f"(d[2]), "+f"(d[3])
        : "r"(a[0]), "r"(a[1]), "r"(a[2]), "r"(a[3]), "r"(bb[0]), "r"(bb[1]));
}
__device__ __forceinline__ void cpa16(uint32_t dst, const float* src, bool pred) {
    int sz = pred ? 16 : 0;
    asm volatile("cp.async.cg.shared.global [%0], [%1], 16, %2;\n"
                 :: "r"(dst), "l"(src), "r"(sz));
}
__device__ __forceinline__ float gelu_exact(float x) {
    return 0.5f * x * (1.0f + erff(x * 0.70710678118654752f));
}

template<int EPI>
__global__ void __launch_bounds__(256) k_gemm2(const float* __restrict__ A,
                                               const float* __restrict__ W,
                                               const float* __restrict__ bias,
                                               const float* __restrict__ addm,
                                               float* __restrict__ D, int M) {
    extern __shared__ float sm[];
    float* As = sm;                 // 2 stages of ASZ
    float* Bs = sm + 2 * ASZ;       // 2 stages of BSZ
    uint32_t sA = (uint32_t)__cvta_generic_to_shared(As);
    uint32_t sB = (uint32_t)__cvta_generic_to_shared(Bs);

    int tid = threadIdx.x, lane = tid & 31, warp = tid >> 5;
    int wm = warp >> 2, wn = warp & 3;          // 2 x 4 warp grid
    int p = lane >> 2, q = lane & 3;
    int row0 = blockIdx.x * 128;

    // async-copy thread mapping
    int ar = tid & 127, ah = tid >> 7;          // A: row ar, k-half ah (16 k each)
    int bk = tid >> 3,  bc = (tid & 7) * 4;     // B: k-row bk, col base bc (+32*i)
    bool arow_ok = (row0 + ar) < M;
    const float* Ag = A + (size_t)(row0 + ar) * kC + ah * 16;
    const float* Wg = W + (size_t)bk * kC + bc;
    uint32_t adst0 = sA + (uint32_t)((ar * APITCH + ah * 16) * 4);
    uint32_t bdst0 = sB + (uint32_t)((bk * BPITCH + bc) * 4);

    auto issue = [&](int kt, int buf) {
        uint32_t ad = adst0 + (uint32_t)(buf * ASZ * 4);
        const float* as = Ag + kt * 32;
#pragma unroll
        for (int i = 0; i < 4; i++) cpa16(ad + i * 16, as + 4 * i, arow_ok);
        uint32_t bd = bdst0 + (uint32_t)(buf * BSZ * 4);
        const float* bs = Wg + (size_t)kt * 32 * kC;
#pragma unroll
        for (int i = 0; i < 8; i++) cpa16(bd + i * 128, bs + 32 * i, true);
    };

    float acc[4][8][4] = {};

    issue(0, 0);
    asm volatile("cp.async.commit_group;\n");

    int mbase = wm * 64, nbase = wn * 64;
#pragma unroll 1
    for (int kt = 0; kt < 8; kt++) {
        int buf = kt & 1;
        if (kt < 7) {
            issue(kt + 1, buf ^ 1);
            asm volatile("cp.async.commit_group;\n");
            asm volatile("cp.async.wait_group 1;\n");
        } else {
            asm volatile("cp.async.wait_group 0;\n");
        }
        __syncthreads();
        const float* Ab = As + buf * ASZ;
        const float* Bb = Bs + buf * BSZ;
#pragma unroll
        for (int kk = 0; kk < 32; kk += 8) {
            uint32_t af[4][4], bf[8][2];
#pragma unroll
            for (int mi = 0; mi < 4; mi++) {
                const float* a0 = Ab + (mbase + mi * 16 + p) * APITCH + kk + q;
                af[mi][0] = f2tf(a0[0]);
                af[mi][1] = f2tf(a0[8 * APITCH]);
                af[mi][2] = f2tf(a0[4]);
                af[mi][3] = f2tf(a0[8 * APITCH + 4]);
            }
#pragma unroll
            for (int ni = 0; ni < 8; ni++) {
                const float* b0 = Bb + (kk + q) * BPITCH + nbase + ni * 8 + p;
                bf[ni][0] = f2tf(b0[0]);
                bf[ni][1] = f2tf(b0[4 * BPITCH]);
            }
#pragma unroll
            for (int mi = 0; mi < 4; mi++)
#pragma unroll
                for (int ni = 0; ni < 8; ni++)
                    mma_tf32(acc[mi][ni], af[mi], bf[ni]);
        }
        __syncthreads();
    }

    // epilogue
#pragma unroll
    for (int mi = 0; mi < 4; mi++) {
        int r1 = row0 + mbase + mi * 16 + p;
        int r2 = r1 + 8;
#pragma unroll
        for (int ni = 0; ni < 8; ni++) {
            int cc = nbase + ni * 8 + 2 * q;
            float2 bv = *(const float2*)(bias + cc);
            float d0 = acc[mi][ni][0] + bv.x, d1 = acc[mi][ni][1] + bv.y;
            float d2 = acc[mi][ni][2] + bv.x, d3 = acc[mi][ni][3] + bv.y;
            if (EPI == 1) {
                if (r1 < M) { float2 a1 = *(const float2*)(addm + (size_t)r1 * kC + cc); d0 += a1.x; d1 += a1.y; }
                if (r2 < M) { float2 a2 = *(const float2*)(addm + (size_t)r2 * kC + cc); d2 += a2.x; d3 += a2.y; }
            }
            if (EPI == 2) {
                d0 = gelu_exact(d0); d1 = gelu_exact(d1);
                d2 = gelu_exact(d2); d3 = gelu_exact(d3);
            }
            if (r1 < M) { float2 o; o.x = d0; o.y = d1; *(float2*)(D + (size_t)r1 * kC + cc) = o; }
            if (r2 < M) { float2 o; o.x = d2; o.y = d3; *(float2*)(D + (size_t)r2 * kC + cc) = o; }
        }
    }
}

// ============ q attention logits: qlog[r][h] = scale*(q[r]·qa_w[:,h] + qa_b[h]) ============
__global__ void __launch_bounds__(256) k_qlog(const float* __restrict__ qa_w,
                                              const float* __restrict__ qa_b, int M) {
    int warp = threadIdx.x >> 5, lane = threadIdx.x & 31;
    int r = blockIdx.x * 8 + warp;
    if (r >= M) return;
    const float* row = g_q + (size_t)r * kC;
    int c0 = lane * 8;
    float4 v0 = *(const float4*)(row + c0);
    float4 v1 = *(const float4*)(row + c0 + 4);
    float vv[8] = {v0.x, v0.y, v0.z, v0.w, v1.x, v1.y, v1.z, v1.w};
    float acc[8] = {};
#pragma unroll
    for (int j = 0; j < 8; j++) {
        const float4* wr = (const float4*)(qa_w + (size_t)(c0 + j) * kH);
        float4 w0 = wr[0], w1 = wr[1];
        acc[0] += vv[j] * w0.x; acc[1] += vv[j] * w0.y;
        acc[2] += vv[j] * w0.z; acc[3] += vv[j] * w0.w;
        acc[4] += vv[j] * w1.x; acc[5] += vv[j] * w1.y;
        acc[6] += vv[j] * w1.z; acc[7] += vv[j] * w1.w;
    }
#pragma unroll
    for (int o = 16; o; o >>= 1)
#pragma unroll
        for (int e = 0; e < 8; e++)
            acc[e] += __shfl_xor_sync(0xffffffffu, acc[e], o);
    if (lane < 8) g_ql[(size_t)r * kH + lane] = (acc[lane] + qa_b[lane]) * kSCALE;
}

// ============ fused per-window pooling: qw,pq,klog,kw,pk -> mq, mkv ============
__global__ void __launch_bounds__(256) k_pool(const float* __restrict__ ka_w,
                                              const float* __restrict__ ka_b) {
    __shared__ int   su[kL];
    __shared__ float sqw[kH][128];
    __shared__ float skw[kH][128];
    __shared__ float spq[kC];
    int tid = threadIdx.x, lane = tid & 31, h = tid >> 5;
    int b = blockIdx.x, n = b / kT, t = b % kT;

    if (tid < kL) {
        int w = tid / kV, v = tid - w * kV;
        int tp = t + w - 2;
        su[tid] = (tp >= 0 && tp < kT) ? (n * kT + tp) * kV + v : kU;
    }
    float wreg[8][8];
#pragma unroll
    for (int j = 0; j < 8; j++) {
        int c = lane + 32 * j;
        const float4* wr = (const float4*)(ka_w + (size_t)c * kH);
        float4 w0 = wr[0], w1 = wr[1];
        wreg[j][0] = w0.x; wreg[j][1] = w0.y; wreg[j][2] = w0.z; wreg[j][3] = w0.w;
        wreg[j][4] = w1.x; wreg[j][5] = w1.y; wreg[j][6] = w1.z; wreg[j][7] = w1.w;
    }
    float kab = (lane < kH) ? ka_b[lane] : 0.f;
    __syncthreads();

    // ---- q-weight softmax (warp h over l) ----
    {
        float lv[4]; float mx = -1e30f;
#pragma unroll
        for (int i = 0; i < 4; i++) {
            int l = lane + 32 * i;
            lv[i] = (l < kL) ? g_ql[(size_t)su[l] * kH + h] : -1e30f;
            mx = fmaxf(mx, lv[i]);
        }
#pragma unroll
        for (int o = 16; o; o >>= 1) mx = fmaxf(mx, __shfl_xor_sync(0xffffffffu, mx, o));
        float sm = 0.f;
#pragma unroll
        for (int i = 0; i < 4; i++) {
            int l = lane + 32 * i;
            lv[i] = (l < kL) ? expf(lv[i] - mx) : 0.f;
            sm += lv[i];
        }
#pragma unroll
        for (int o = 16; o; o >>= 1) sm += __shfl_xor_sync(0xffffffffu, sm, o);
        float inv = 1.f / sm;
#pragma unroll
        for (int i = 0; i < 4; i++) {
            int l = lane + 32 * i;
            if (l < kL) sqw[h][l] = lv[i] * inv;
        }
    }
    __syncthreads();

    // ---- pass A: pq (softmax-pooled q) and mq (window-mean q) ----
    float pq = 0.f;
#pragma unroll
    for (int v = 0; v < kV; v++) {
        float a = 0.f;
#pragma unroll
        for (int w = 0; w < kWIN; w++) {
            int l = w * kV + v;
            float val = g_q[(size_t)su[l] * kC + tid];
            pq += sqw[h][l] * val;
            a  += val;
        }
        g_nx[((size_t)b * kV + v) * kC + tid] = a * 0.2f;   // mq (reuses g_nx)
    }
    spq[tid] = pq;
    __syncthreads();

    // ---- pass B: k logits (warp per l, strided) ----
    float pqr[8];
#pragma unroll
    for (int j = 0; j < 8; j++) pqr[j] = spq[lane + 32 * j];
    for (int l = h; l < kL; l += kH) {
        const float* kr = g_k + (size_t)su[l] * kC;
        float acc[8] = {};
#pragma unroll
        for (int j = 0; j < 8; j++) {
            float kp = kr[lane + 32 * j] * pqr[j];
#pragma unroll
            for (int e = 0; e < 8; e++) acc[e] += kp * wreg[j][e];
        }
#pragma unroll
        for (int o = 16; o; o >>= 1)
#pragma unroll
            for (int e = 0; e < 8; e++)
                acc[e] += __shfl_xor_sync(0xffffffffu, acc[e], o);
        if (lane < kH) skw[lane][l] = (acc[lane] + kab) * kSCALE;
    }
    __syncthreads();

    // ---- k-weight softmax ----
    {
        float lv[4]; float mx = -1e30f;
#pragma unroll
        for (int i = 0; i < 4; i++) {
            int l = lane + 32 * i;
            lv[i] = (l < kL) ? skw[h][l] : -1e30f;
            mx = fmaxf(mx, lv[i]);
        }
#pragma unroll
        for (int o = 16; o; o >>= 1) mx = fmaxf(mx, __shfl_xor_sync(0xffffffffu, mx, o));
        float sm = 0.f;
#pragma unroll
        for (int i = 0; i < 4; i++) {
            int l = lane + 32 * i;
            lv[i] = (l < kL) ? expf(lv[i] - mx) : 0.f;
            sm += lv[i];
        }
#pragma unroll
        for (int o = 16; o; o >>= 1) sm += __shfl_xor_sync(0xffffffffu, sm, o);
        float inv = 1.f / sm;
#pragma unroll
        for (int i = 0; i < 4; i++) {
            int l = lane + 32 * i;
            if (l < kL) skw[h][l] = lv[i] * inv;
        }
    }
    __syncthreads();

    // ---- pass C: pk, mv, mkv = pk*mv ----
    float pk = 0.f;
    float mva[kV];
#pragma unroll
    for (int v = 0; v < kV; v++) {
        float a = 0.f;
#pragma unroll
        for (int w = 0; w < kWIN; w++) {
            int l = w * kV + v;
            int u = su[l];
            pk += skw[h][l] * g_k[(size_t)u * kC + tid];
            a  += g_v[(size_t)u * kC + tid];
        }
        mva[v] = a * 0.2f;
    }
#pragma unroll
    for (int v = 0; v < kV; v++)
        g_mkv[((size_t)b * kV + v) * kC + tid] = pk * mva[v];
}

// ============ plain row LayerNorm (FFN input): g_k(attraw) -> g_v(f) ============
__global__ void __launch_bounds__(256) k_ln_rows(const float* __restrict__ g,
                                                 const float* __restrict__ b) {
    int warp = threadIdx.x >> 5, lane = threadIdx.x & 31;
    int r = blockIdx.x * 8 + warp;
    const float* row = g_k + (size_t)r * kC;
    float vv[8]; float s = 0.f, sq = 0.f;
#pragma unroll
    for (int j = 0; j < 8; j++) {
        float x = row[lane + 32 * j];
        vv[j] = x; s += x; sq += x * x;
    }
#pragma unroll
    for (int o = 16; o; o >>= 1) {
        s  += __shfl_xor_sync(0xffffffffu, s,  o);
        sq += __shfl_xor_sync(0xffffffffu, sq, o);
    }
    float mean = s * (1.f / kC);
    float var  = sq * (1.f / kC) - mean * mean;
    float rstd = rsqrtf(var + 1e-5f);
#pragma unroll
    for (int j = 0; j < 8; j++) {
        int c = lane + 32 * j;
        g_v[(size_t)r * kC + c] = (vv[j] - mean) * rstd * g[c] + b[c];
    }
}

// ============ transpose y (u,c) -> out (n,c,t,v) ============
__global__ void __launch_bounds__(256) k_out(float* __restrict__ out) {
    __shared__ float sy[kV][257];
    int b = blockIdx.x, n = b / kT, t = b % kT;
    int tid = threadIdx.x;
#pragma unroll
    for (int v = 0; v < kV; v++)
        sy[v][tid] = g_mkv[((size_t)b * kV + v) * kC + tid];
    __syncthreads();
    float* ob = out + (size_t)n * kXN + t * kV;
    for (int i = tid; i < kV * kC; i += 256) {
        int c = i / kV, v = i - c * kV;
        ob[(size_t)c * kTV + v] = sy[v][c];
    }
}

// ===================================================================================
extern "C" void kernel_launch(void* const* d_in, const int* in_sizes, int n_in,
                              void* d_out, int out_size) {
    const float* x    = (const float*)d_in[0];
    const float* ln1g = (const float*)d_in[1];
    const float* ln1b = (const float*)d_in[2];
    const float* q_w  = (const float*)d_in[3];
    const float* q_b  = (const float*)d_in[4];
    const float* qa_w = (const float*)d_in[5];
    const float* qa_b = (const float*)d_in[6];
    const float* k_w  = (const float*)d_in[7];
    const float* k_b  = (const float*)d_in[8];
    const float* ka_w = (const float*)d_in[9];
    const float* ka_b = (const float*)d_in[10];
    const float* v_w  = (const float*)d_in[11];
    const float* v_b  = (const float*)d_in[12];
    const float* t_w  = (const float*)d_in[13];
    const float* t_b  = (const float*)d_in[14];
    const float* p_w  = (const float*)d_in[15];
    const float* p_b  = (const float*)d_in[16];
    const float* ffng = (const float*)d_in[17];
    const float* ffnb = (const float*)d_in[18];
    const float* w1   = (const float*)d_in[19];
    const float* b1   = (const float*)d_in[20];
    const float* w2   = (const float*)d_in[21];
    const float* b2   = (const float*)d_in[22];
    float* out = (float*)d_out;

    float *p_nx, *p_q, *p_k, *p_v, *p_xr, *p_mkv;
    cudaGetSymbolAddress((void**)&p_nx,  g_nx);
    cudaGetSymbolAddress((void**)&p_q,   g_q);
    cudaGetSymbolAddress((void**)&p_k,   g_k);
    cudaGetSymbolAddress((void**)&p_v,   g_v);
    cudaGetSymbolAddress((void**)&p_xr,  g_xr);
    cudaGetSymbolAddress((void**)&p_mkv, g_mkv);

    cudaFuncSetAttribute(k_gemm2<0>, cudaFuncAttributeMaxDynamicSharedMemorySize, GEMM_SMEM);
    cudaFuncSetAttribute(k_gemm2<1>, cudaFuncAttributeMaxDynamicSharedMemorySize, GEMM_SMEM);
    cudaFuncSetAttribute(k_gemm2<2>, cudaFuncAttributeMaxDynamicSharedMemorySize, GEMM_SMEM);

    int g1 = (kM1 + 127) / 128;   // 401
    int g2 = (kU  + 127) / 128;   // 400

    // 1) LN of unique tokens (+ raw gather for residual)
    k_ln_x<<<(kM1 + 31) / 32, 256>>>(x, ln1g, ln1b);
    // 2-4) q, k, v projections
    k_gemm2<0><<<g1, 256, GEMM_SMEM>>>(p_nx, q_w, q_b, nullptr, p_q, kM1);
    k_gemm2<0><<<g1, 256, GEMM_SMEM>>>(p_nx, k_w, k_b, nullptr, p_k, kM1);
    k_gemm2<0><<<g1, 256, GEMM_SMEM>>>(p_nx, v_w, v_b, nullptr, p_v, kM1);
    // 5) q attention logits
    k_qlog<<<(kM1 + 7) / 8, 256>>>(qa_w, qa_b, kM1);
    // 6) fused pooling -> mq (in g_nx), mkv
    k_pool<<<kB, 256>>>(ka_w, ka_b);
    // 7) t1 = mkv @ t_w + t_b + mq       (-> g_q)
    k_gemm2<1><<<g2, 256, GEMM_SMEM>>>(p_mkv, t_w, t_b, p_nx, p_q, kU);
    // 8) attraw = t1 @ p_w + p_b + xr    (-> g_k)
    k_gemm2<1><<<g2, 256, GEMM_SMEM>>>(p_q, p_w, p_b, p_xr, p_k, kU);
    // 9) f = LN(attraw)                  (-> g_v)
    k_ln_rows<<<kU / 8, 256>>>(ffng, ffnb);
    // 10) h1 = gelu(f @ w1 + b1)         (-> g_nx)
    k_gemm2<2><<<g2, 256, GEMM_SMEM>>>(p_v, w1, b1, nullptr, p_nx, kU);
    // 11) y = h1 @ w2 + b2 + attraw      (-> g_mkv)
    k_gemm2<1><<<g2, 256, GEMM_SMEM>>>(p_nx, w2, b2, p_k, p_mkv, kU);
    // 12) transpose to (N,C,T,V)
    k_out<<<kB, 256>>>(out);
}